// round 2
// baseline (speedup 1.0000x reference)
#include <cuda_runtime.h>
#include <math.h>

// Problem constants (fixed shapes)
#define B_ROWS  4096
#define N_NODES 2048
#define N_IN    512
#define N_EVAL  1536
#define N_OUT   256
#define CHUNK   128
#define NCHUNK  12

// Persistent activation scratch: [B_ROWS, N_NODES] fp32 (32 MB)
__device__ float g_outputs[(size_t)B_ROWS * N_NODES];

// SGEMM tile config
#define BM 32
#define BN 128
#define BK 16

// ---------------------------------------------------------------------------
// Fused chunk kernel: Z[BM,128] = outputs[:, :P] @ W[i0:i0+128, :P]^T + b,
// then sequential triangular epilogue + sigmoid, writing o back to g_outputs.
// grid: 128 blocks (4096/32 rows), block: 256 threads.
// ---------------------------------------------------------------------------
__global__ __launch_bounds__(256) void chunk_kernel(const float* __restrict__ W,
                                                    const float* __restrict__ bias,
                                                    int i0)
{
    const int P = N_IN + i0;              // prefix length (multiple of 16)

    __shared__ float As[2][BK * 34];      // [k][m], padded
    __shared__ float Bs[2][BK * 132];     // [k][c], padded (132 % 4 == 0 for float4)
    __shared__ float Zs[CHUNK * 33];      // [c][m], padded

    const int tid  = threadIdx.x;
    const int brow = blockIdx.x * BM;

    // compute-thread mapping: 16x16 thread grid, each does 2 rows x 8 cols
    const int tx = tid & 15;
    const int ty = tid >> 4;
    const int r0 = 2 * ty;                // local row 0..30
    const int c0 = 8 * tx;                // local col 0..120

    // global-load mappings
    const int am = tid >> 3;              // A: row 0..31
    const int ak = (tid & 7) * 2;         // A: k offset (even)
    const int bc = tid >> 1;              // B: chunk-col 0..127
    const int bk = (tid & 1) * 8;         // B: k offset 0 or 8

    const float* Ag = g_outputs + (size_t)(brow + am) * N_NODES;
    const float* Bg = W + (size_t)(i0 + bc) * N_NODES;

    float acc[2][8];
#pragma unroll
    for (int i = 0; i < 2; i++)
#pragma unroll
        for (int j = 0; j < 8; j++) acc[i][j] = 0.f;

    const int nIter = P / BK;

    // preload tile 0
    {
        float2 av = *(const float2*)(Ag + ak);
        As[0][(ak    ) * 34 + am] = av.x;
        As[0][(ak + 1) * 34 + am] = av.y;
        float4 b0 = *(const float4*)(Bg + bk);
        float4 b1 = *(const float4*)(Bg + bk + 4);
        Bs[0][(bk + 0) * 132 + bc] = b0.x;
        Bs[0][(bk + 1) * 132 + bc] = b0.y;
        Bs[0][(bk + 2) * 132 + bc] = b0.z;
        Bs[0][(bk + 3) * 132 + bc] = b0.w;
        Bs[0][(bk + 4) * 132 + bc] = b1.x;
        Bs[0][(bk + 5) * 132 + bc] = b1.y;
        Bs[0][(bk + 6) * 132 + bc] = b1.z;
        Bs[0][(bk + 7) * 132 + bc] = b1.w;
    }
    __syncthreads();

    int buf = 0;
    for (int t = 0; t < nIter; t++) {
        float2 av;
        float4 b0v, b1v;
        const bool more = (t + 1 < nIter);
        if (more) {
            const float* Ag2 = Ag + (t + 1) * BK;
            const float* Bg2 = Bg + (t + 1) * BK;
            av  = *(const float2*)(Ag2 + ak);
            b0v = *(const float4*)(Bg2 + bk);
            b1v = *(const float4*)(Bg2 + bk + 4);
        }

        // compute on current buffer
#pragma unroll
        for (int kk = 0; kk < BK; kk++) {
            float2 a  = *(const float2*)&As[buf][kk * 34 + r0];
            float4 bb0 = *(const float4*)&Bs[buf][kk * 132 + c0];
            float4 bb1 = *(const float4*)&Bs[buf][kk * 132 + c0 + 4];
            float bv[8] = {bb0.x, bb0.y, bb0.z, bb0.w, bb1.x, bb1.y, bb1.z, bb1.w};
#pragma unroll
            for (int j = 0; j < 8; j++) {
                acc[0][j] += a.x * bv[j];
                acc[1][j] += a.y * bv[j];
            }
        }

        if (more) {
            const int nb = buf ^ 1;
            As[nb][(ak    ) * 34 + am] = av.x;
            As[nb][(ak + 1) * 34 + am] = av.y;
            Bs[nb][(bk + 0) * 132 + bc] = b0v.x;
            Bs[nb][(bk + 1) * 132 + bc] = b0v.y;
            Bs[nb][(bk + 2) * 132 + bc] = b0v.z;
            Bs[nb][(bk + 3) * 132 + bc] = b0v.w;
            Bs[nb][(bk + 4) * 132 + bc] = b1v.x;
            Bs[nb][(bk + 5) * 132 + bc] = b1v.y;
            Bs[nb][(bk + 6) * 132 + bc] = b1v.z;
            Bs[nb][(bk + 7) * 132 + bc] = b1v.w;
        }
        __syncthreads();
        buf ^= 1;
    }

    // stage Z (+bias) into smem as [c][m]
    const float* bptr = bias + i0;
#pragma unroll
    for (int j = 0; j < 8; j++) {
        float bv = bptr[c0 + j];
        Zs[(c0 + j) * 33 + r0    ] = acc[0][j] + bv;
        Zs[(c0 + j) * 33 + r0 + 1] = acc[1][j] + bv;
    }
    __syncthreads();

    // -----------------------------------------------------------------------
    // Triangular epilogue. Each warp owns 4 batch rows; within a row, 8 lanes
    // (sub = lane&7) split the intra-chunk dot product, butterfly-reduce.
    // Rows are independent -> only __syncwarp per node.
    // -----------------------------------------------------------------------
    {
        const int warp = tid >> 5;
        const int lane = tid & 31;
        const int mloc = lane >> 3;       // 0..3
        const int sub  = lane & 7;        // 0..7
        const int m    = warp * 4 + mloc; // 0..31

        for (int c = 0; c < CHUNK; c++) {
            const float* wrow = W + (size_t)(i0 + c) * N_NODES + P;
            float s = 0.f;
            for (int d = sub; d < c; d += 8)
                s += wrow[d] * Zs[d * 33 + m];
            s += __shfl_xor_sync(0xffffffffu, s, 1);
            s += __shfl_xor_sync(0xffffffffu, s, 2);
            s += __shfl_xor_sync(0xffffffffu, s, 4);
            float z  = Zs[c * 33 + m] + s;
            float t5 = fminf(fmaxf(5.0f * z, -60.0f), 60.0f);
            float o  = 1.0f / (1.0f + expf(-t5));
            if (sub == 0) Zs[c * 33 + m] = o;
            __syncwarp();
        }
    }
    __syncthreads();

    // write back: g_outputs[brow+m][P + c]
    {
        const int m2  = tid >> 3;          // 0..31
        const int cc0 = (tid & 7) * 16;    // 0..112
        float* dst = g_outputs + (size_t)(brow + m2) * N_NODES + P + cc0;
#pragma unroll
        for (int j = 0; j < 16; j++)
            dst[j] = Zs[(cc0 + j) * 33 + m2];
    }
}

// ---------------------------------------------------------------------------
__global__ void init_kernel(const float* __restrict__ x)
{
    int idx = blockIdx.x * blockDim.x + threadIdx.x;
    if (idx < B_ROWS * N_IN) {
        int r = idx >> 9;          // /512
        int c = idx & 511;
        g_outputs[(size_t)r * N_NODES + c] = x[idx];
    }
}

__global__ void copy_kernel(float* __restrict__ out)
{
    int idx = blockIdx.x * blockDim.x + threadIdx.x;
    if (idx < B_ROWS * N_OUT) {
        int r = idx >> 8;          // /256
        int c = idx & 255;
        out[idx] = g_outputs[(size_t)r * N_NODES + (N_NODES - N_OUT) + c];
    }
}

// ---------------------------------------------------------------------------
extern "C" void kernel_launch(void* const* d_in, const int* in_sizes, int n_in,
                              void* d_out, int out_size)
{
    (void)in_sizes; (void)n_in; (void)out_size;
    const float* x  = (const float*)d_in[0];
    const float* W  = (const float*)d_in[1];
    const float* b  = (const float*)d_in[2];
    float* out = (float*)d_out;

    init_kernel<<<(B_ROWS * N_IN + 255) / 256, 256>>>(x);
    for (int k = 0; k < NCHUNK; k++)
        chunk_kernel<<<B_ROWS / BM, 256>>>(W, b, k * CHUNK);
    copy_kernel<<<(B_ROWS * N_OUT + 255) / 256, 256>>>(out);
}

// round 3
// speedup vs baseline: 1.8469x; 1.8469x over previous
#include <cuda_runtime.h>
#include <math.h>

// Problem constants (fixed shapes)
#define B_ROWS  4096
#define N_NODES 2048
#define N_IN    512
#define N_EVAL  1536
#define N_OUT   256
#define CHUNK   128
#define NCHUNK  12

// Persistent scratch
__device__ float g_outputs[(size_t)B_ROWS * N_NODES];   // 32 MB activations
__device__ float g_z[(size_t)B_ROWS * CHUNK];           // 2 MB chunk pre-activations

typedef unsigned long long u64;

__device__ __forceinline__ u64 pack2(float x, float y) {
    u64 r; asm("mov.b64 %0, {%1,%2};" : "=l"(r) : "f"(x), "f"(y)); return r;
}
__device__ __forceinline__ void ffma2(u64& d, u64 a, u64 b) {
    asm("fma.rn.f32x2 %0, %1, %2, %0;" : "+l"(d) : "l"(a), "l"(b));
}
__device__ __forceinline__ float2 unpack2(u64 v) {
    float2 f; asm("mov.b64 {%0,%1}, %2;" : "=f"(f.x), "=f"(f.y) : "l"(v)); return f;
}

// ---------------------------------------------------------------------------
// GEMM: g_z[4096,128] = g_outputs[:, :P] @ W[i0:i0+128, :P]^T
// BM=32, BN=128, BK=16, 256 threads, grid = 128 blocks.
// Thread tile: 4 rows (2 f32x2 pairs) x 4 cols -> 8 FFMA2 per kk.
// Warp layout: all lanes share the A fragment (broadcast LDS.128).
// ---------------------------------------------------------------------------
#define BKt 16
#define AS_STRIDE 36
#define BS_STRIDE 132

__global__ __launch_bounds__(256) void gemm_chunk(const float* __restrict__ W,
                                                  int i0)
{
    const int P = N_IN + i0;                 // multiple of 16

    __shared__ float As[2][BKt * AS_STRIDE];
    __shared__ float Bs[2][BKt * BS_STRIDE];

    const int tid  = threadIdx.x;
    const int brow = blockIdx.x * 32;
    const int warp = tid >> 5;
    const int lane = tid & 31;

    const int r0 = 4 * warp;                 // 0..28 (rows of this warp)
    const int c0 = 4 * lane;                 // 0..124 (cols of this thread)

    // A global->smem mapping: thread loads 2 consecutive k's of one row
    const int am = tid >> 3;                 // 0..31
    const int ak = (tid & 7) * 2;            // 0..14 even
    // B global->smem mapping: lane = column (conflict-free STS), 8 k's per thread
    const int bcol = 32 * (warp >> 1) + lane;   // 0..127
    const int bkh  = (warp & 1) * 8;            // 0 or 8

    const float* Ag = g_outputs + (size_t)(brow + am) * N_NODES + ak;
    const float* Bg = W + (size_t)(i0 + bcol) * N_NODES + bkh;

    u64 acc[2][4];
#pragma unroll
    for (int p = 0; p < 2; p++)
#pragma unroll
        for (int j = 0; j < 4; j++) acc[p][j] = 0ULL;

    const int nIter = P / BKt;

    // preload tile 0
    {
        float2 av = *(const float2*)Ag;
        float4 b0 = *(const float4*)Bg;
        float4 b1 = *(const float4*)(Bg + 4);
        As[0][(ak    ) * AS_STRIDE + am] = av.x;
        As[0][(ak + 1) * AS_STRIDE + am] = av.y;
        Bs[0][(bkh + 0) * BS_STRIDE + bcol] = b0.x;
        Bs[0][(bkh + 1) * BS_STRIDE + bcol] = b0.y;
        Bs[0][(bkh + 2) * BS_STRIDE + bcol] = b0.z;
        Bs[0][(bkh + 3) * BS_STRIDE + bcol] = b0.w;
        Bs[0][(bkh + 4) * BS_STRIDE + bcol] = b1.x;
        Bs[0][(bkh + 5) * BS_STRIDE + bcol] = b1.y;
        Bs[0][(bkh + 6) * BS_STRIDE + bcol] = b1.z;
        Bs[0][(bkh + 7) * BS_STRIDE + bcol] = b1.w;
    }
    __syncthreads();

    int buf = 0;
    for (int t = 0; t < nIter; t++) {
        const bool more = (t + 1 < nIter);
        float2 av;  float4 b0v, b1v;
        if (more) {
            av  = *(const float2*)(Ag + (t + 1) * BKt);
            b0v = *(const float4*)(Bg + (t + 1) * BKt);
            b1v = *(const float4*)(Bg + (t + 1) * BKt + 4);
        }

        // register-double-buffered compute over the current smem tile
        float4 af[2], bf[2];
        af[0] = *(const float4*)&As[buf][r0];
        bf[0] = *(const float4*)&Bs[buf][c0];
#pragma unroll
        for (int kk = 0; kk < BKt; kk++) {
            const int cur = kk & 1;
            if (kk < BKt - 1) {
                af[cur ^ 1] = *(const float4*)&As[buf][(kk + 1) * AS_STRIDE + r0];
                bf[cur ^ 1] = *(const float4*)&Bs[buf][(kk + 1) * BS_STRIDE + c0];
            }
            u64 a01 = pack2(af[cur].x, af[cur].y);
            u64 a23 = pack2(af[cur].z, af[cur].w);
            u64 bb0 = pack2(bf[cur].x, bf[cur].x);
            u64 bb1 = pack2(bf[cur].y, bf[cur].y);
            u64 bb2 = pack2(bf[cur].z, bf[cur].z);
            u64 bb3 = pack2(bf[cur].w, bf[cur].w);
            ffma2(acc[0][0], a01, bb0);
            ffma2(acc[0][1], a01, bb1);
            ffma2(acc[0][2], a01, bb2);
            ffma2(acc[0][3], a01, bb3);
            ffma2(acc[1][0], a23, bb0);
            ffma2(acc[1][1], a23, bb1);
            ffma2(acc[1][2], a23, bb2);
            ffma2(acc[1][3], a23, bb3);
        }

        if (more) {
            const int nb = buf ^ 1;
            As[nb][(ak    ) * AS_STRIDE + am] = av.x;
            As[nb][(ak + 1) * AS_STRIDE + am] = av.y;
            Bs[nb][(bkh + 0) * BS_STRIDE + bcol] = b0v.x;
            Bs[nb][(bkh + 1) * BS_STRIDE + bcol] = b0v.y;
            Bs[nb][(bkh + 2) * BS_STRIDE + bcol] = b0v.z;
            Bs[nb][(bkh + 3) * BS_STRIDE + bcol] = b0v.w;
            Bs[nb][(bkh + 4) * BS_STRIDE + bcol] = b1v.x;
            Bs[nb][(bkh + 5) * BS_STRIDE + bcol] = b1v.y;
            Bs[nb][(bkh + 6) * BS_STRIDE + bcol] = b1v.z;
            Bs[nb][(bkh + 7) * BS_STRIDE + bcol] = b1v.w;
        }
        __syncthreads();
        buf ^= 1;
    }

    // write Z: 4 rows x float4
#pragma unroll
    for (int p = 0; p < 2; p++) {
        float2 u0 = unpack2(acc[p][0]);
        float2 u1 = unpack2(acc[p][1]);
        float2 u2 = unpack2(acc[p][2]);
        float2 u3 = unpack2(acc[p][3]);
        float4 lo = make_float4(u0.x, u1.x, u2.x, u3.x);
        float4 hi = make_float4(u0.y, u1.y, u2.y, u3.y);
        float* zp = g_z + (size_t)(brow + r0 + 2 * p) * CHUNK + c0;
        *(float4*)zp = lo;
        *(float4*)(zp + CHUNK) = hi;
    }
}

// ---------------------------------------------------------------------------
// Triangular epilogue: one warp per batch row, 4096 warps (512 blocks x 8).
// Lane l owns nodes {l, 32+l, 64+l, 96+l}. W's strict-lower-tri zeros make
// masking unnecessary (W[i0+c][P+d] == 0 for d >= c).
// ---------------------------------------------------------------------------
__global__ __launch_bounds__(256) void epi_chunk(const float* __restrict__ W,
                                                 const float* __restrict__ bias,
                                                 int i0)
{
    const int P    = N_IN + i0;
    const int tid  = threadIdx.x;
    const int warp = tid >> 5;
    const int lane = tid & 31;
    const int m    = blockIdx.x * 8 + warp;

    const float* Zr = g_z + (size_t)m * CHUNK;

    float zv[4], ov[4];
#pragma unroll
    for (int q = 0; q < 4; q++) {
        zv[q] = Zr[32 * q + lane] + bias[i0 + 32 * q + lane];
        ov[q] = 0.f;
    }

    const float* Wp = W + (size_t)i0 * N_NODES + P + lane;

    // depth-2 software pipeline of W rows
    float wcur[4], wnxt[4];
#pragma unroll
    for (int q = 0; q < 4; q++) {
        wcur[q] = Wp[32 * q];
        wnxt[q] = Wp[N_NODES + 32 * q];
    }

#pragma unroll
    for (int q = 0; q < 4; q++) {
        for (int cc = 0; cc < 32; cc++) {
            const int c = 32 * q + cc;
            float wpre0 = 0.f, wpre1 = 0.f, wpre2 = 0.f, wpre3 = 0.f;
            if (c + 2 < CHUNK) {
                const float* wr = Wp + (size_t)(c + 2) * N_NODES;
                wpre0 = wr[0];  wpre1 = wr[32];
                wpre2 = wr[64]; wpre3 = wr[96];
            }
            float s = wcur[0] * ov[0];
            s = fmaf(wcur[1], ov[1], s);
            s = fmaf(wcur[2], ov[2], s);
            s = fmaf(wcur[3], ov[3], s);
            s += __shfl_xor_sync(0xffffffffu, s, 16);
            s += __shfl_xor_sync(0xffffffffu, s, 8);
            s += __shfl_xor_sync(0xffffffffu, s, 4);
            s += __shfl_xor_sync(0xffffffffu, s, 2);
            s += __shfl_xor_sync(0xffffffffu, s, 1);
            float z  = __shfl_sync(0xffffffffu, zv[q], cc) + s;
            float t5 = fminf(fmaxf(5.0f * z, -60.0f), 60.0f);
            float o  = __fdividef(1.0f, 1.0f + __expf(-t5));
            if (lane == cc) ov[q] = o;
            wcur[0] = wnxt[0]; wcur[1] = wnxt[1];
            wcur[2] = wnxt[2]; wcur[3] = wnxt[3];
            wnxt[0] = wpre0;  wnxt[1] = wpre1;
            wnxt[2] = wpre2;  wnxt[3] = wpre3;
        }
    }

    float* dst = g_outputs + (size_t)m * N_NODES + P + lane;
#pragma unroll
    for (int q = 0; q < 4; q++) dst[32 * q] = ov[q];
}

// ---------------------------------------------------------------------------
__global__ void init_kernel(const float4* __restrict__ x)
{
    int idx = blockIdx.x * blockDim.x + threadIdx.x;   // over 4096*128 float4s
    if (idx < B_ROWS * (N_IN / 4)) {
        int r = idx >> 7;            // /128
        int c = idx & 127;
        ((float4*)g_outputs)[(size_t)r * (N_NODES / 4) + c] = x[idx];
    }
}

__global__ void copy_kernel(float4* __restrict__ out)
{
    int idx = blockIdx.x * blockDim.x + threadIdx.x;   // over 4096*64 float4s
    if (idx < B_ROWS * (N_OUT / 4)) {
        int r = idx >> 6;            // /64
        int c = idx & 63;
        out[idx] = ((const float4*)g_outputs)[(size_t)r * (N_NODES / 4) +
                                              (N_NODES - N_OUT) / 4 + c];
    }
}

// ---------------------------------------------------------------------------
extern "C" void kernel_launch(void* const* d_in, const int* in_sizes, int n_in,
                              void* d_out, int out_size)
{
    (void)in_sizes; (void)n_in; (void)out_size;
    const float* x  = (const float*)d_in[0];
    const float* W  = (const float*)d_in[1];
    const float* b  = (const float*)d_in[2];
    float* out = (float*)d_out;

    init_kernel<<<(B_ROWS * (N_IN / 4) + 255) / 256, 256>>>((const float4*)x);
    for (int k = 0; k < NCHUNK; k++) {
        gemm_chunk<<<B_ROWS / 32, 256>>>(W, k * CHUNK);
        epi_chunk<<<B_ROWS / 8, 256>>>(W, b, k * CHUNK);
    }
    copy_kernel<<<(B_ROWS * (N_OUT / 4) + 255) / 256, 256>>>((float4*)out);
}

// round 7
// speedup vs baseline: 3.5714x; 1.9337x over previous
#include <cuda_runtime.h>
#include <math.h>

// Problem constants (fixed shapes)
#define B_ROWS  4096
#define N_NODES 2048
#define N_IN    512
#define N_OUT   256
#define CHUNK   128
#define NCHUNK  12
#define KSPLIT  4

// Persistent scratch
__device__ float g_outputs[(size_t)B_ROWS * N_NODES];            // 32 MB activations
__device__ float g_zp[(size_t)KSPLIT * B_ROWS * CHUNK];          // 8 MB K-split partials

typedef unsigned long long u64;

__device__ __forceinline__ u64 pack2(float x, float y) {
    u64 r; asm("mov.b64 %0, {%1,%2};" : "=l"(r) : "f"(x), "f"(y)); return r;
}
__device__ __forceinline__ void ffma2(u64& d, u64 a, u64 b) {
    asm("fma.rn.f32x2 %0, %1, %2, %0;" : "+l"(d) : "l"(a), "l"(b));
}
__device__ __forceinline__ float2 unpack2(u64 v) {
    float2 f; asm("mov.b64 {%0,%1}, %2;" : "=f"(f.x), "=f"(f.y) : "l"(v)); return f;
}

__device__ __forceinline__ float sig5(float z) {
    float t = fminf(fmaxf(5.0f * z, -60.0f), 60.0f);
    return __fdividef(1.0f, 1.0f + __expf(-t));
}

// ---------------------------------------------------------------------------
// GEMM: g_zp[ks][4096,128] = outputs[:, k0:k0+P/4] @ W[i0:i0+128, k0:k0+P/4]^T
// BM=64, BN=128, BK=16, 256 threads, grid = (64 rowblocks, 4 ksplits).
// Thread tile 8 rows x 4 cols = 16 FFMA2/kk, zero pack MOVs in hot loop:
//   A smem [k][m]      -> row-pairs load as packed u64 (LDS.128 -> ulonglong2)
//   B smem [k][2c] dup -> (b,b) pairs load as packed u64
// ---------------------------------------------------------------------------
#define BM   64
#define BN   128
#define BKt  16
#define ASTR 68
#define BSTR 264

__global__ __launch_bounds__(256, 2) void gemm_chunk(const float* __restrict__ W,
                                                     int i0)
{
    const int P     = N_IN + i0;          // multiple of 128+512
    const int kq    = P / KSPLIT;         // multiple of 16
    const int k0    = blockIdx.y * kq;
    const int nIter = kq / BKt;

    __shared__ float As[2][BKt * ASTR];
    __shared__ float Bs[2][BKt * BSTR];

    const int tid  = threadIdx.x;
    const int brow = blockIdx.x * BM;
    const int w    = tid >> 5;
    const int lane = tid & 31;
    const int wr   = w >> 1;              // 0..3
    const int wc   = w & 1;               // 0..1
    const int g    = lane >> 4;           // 0..1
    const int t    = lane & 15;           // 0..15
    const int r0   = 16 * wr + 8 * g;     // thread rows r0..r0+7
    const int c0   = 64 * wc + 4 * t;     // thread cols c0..c0+3

    // global loader mappings
    const int arow = tid >> 2;            // 0..63
    const int ak   = (tid & 3) * 4;       // 0,4,8,12
    const int bcol = tid >> 1;            // 0..127
    const int bk   = (tid & 1) * 8;       // 0,8

    const float* Ag = g_outputs + (size_t)(brow + arow) * N_NODES + k0 + ak;
    const float* Bg = W + (size_t)(i0 + bcol) * N_NODES + k0 + bk;

    u64 acc[4][4];
#pragma unroll
    for (int p = 0; p < 4; p++)
#pragma unroll
        for (int j = 0; j < 4; j++) acc[p][j] = 0ULL;

    // ---- preload tile 0
    {
        float4 av = *(const float4*)Ag;
        float4 b0 = *(const float4*)Bg;
        float4 b1 = *(const float4*)(Bg + 4);
        As[0][(ak + 0) * ASTR + arow] = av.x;
        As[0][(ak + 1) * ASTR + arow] = av.y;
        As[0][(ak + 2) * ASTR + arow] = av.z;
        As[0][(ak + 3) * ASTR + arow] = av.w;
        *(u64*)&Bs[0][(bk + 0) * BSTR + 2 * bcol] = pack2(b0.x, b0.x);
        *(u64*)&Bs[0][(bk + 1) * BSTR + 2 * bcol] = pack2(b0.y, b0.y);
        *(u64*)&Bs[0][(bk + 2) * BSTR + 2 * bcol] = pack2(b0.z, b0.z);
        *(u64*)&Bs[0][(bk + 3) * BSTR + 2 * bcol] = pack2(b0.w, b0.w);
        *(u64*)&Bs[0][(bk + 4) * BSTR + 2 * bcol] = pack2(b1.x, b1.x);
        *(u64*)&Bs[0][(bk + 5) * BSTR + 2 * bcol] = pack2(b1.y, b1.y);
        *(u64*)&Bs[0][(bk + 6) * BSTR + 2 * bcol] = pack2(b1.z, b1.z);
        *(u64*)&Bs[0][(bk + 7) * BSTR + 2 * bcol] = pack2(b1.w, b1.w);
    }
    __syncthreads();

    int buf = 0;
    for (int it = 0; it < nIter; it++) {
        const bool more = (it + 1 < nIter);
        float4 av, b0v, b1v;
        if (more) {
            av  = *(const float4*)(Ag + (it + 1) * BKt);
            b0v = *(const float4*)(Bg + (it + 1) * BKt);
            b1v = *(const float4*)(Bg + (it + 1) * BKt + 4);
        }

        // register-double-buffered compute over current smem tile
        ulonglong2 afA[2], afB[2], bfA[2], bfB[2];
        afA[0] = *(const ulonglong2*)&As[buf][r0];
        afB[0] = *(const ulonglong2*)&As[buf][r0 + 4];
        bfA[0] = *(const ulonglong2*)&Bs[buf][2 * c0];
        bfB[0] = *(const ulonglong2*)&Bs[buf][2 * c0 + 4];
#pragma unroll
        for (int kk = 0; kk < BKt; kk++) {
            const int cur = kk & 1;
            if (kk < BKt - 1) {
                afA[cur ^ 1] = *(const ulonglong2*)&As[buf][(kk + 1) * ASTR + r0];
                afB[cur ^ 1] = *(const ulonglong2*)&As[buf][(kk + 1) * ASTR + r0 + 4];
                bfA[cur ^ 1] = *(const ulonglong2*)&Bs[buf][(kk + 1) * BSTR + 2 * c0];
                bfB[cur ^ 1] = *(const ulonglong2*)&Bs[buf][(kk + 1) * BSTR + 2 * c0 + 4];
            }
            ffma2(acc[0][0], afA[cur].x, bfA[cur].x);
            ffma2(acc[0][1], afA[cur].x, bfA[cur].y);
            ffma2(acc[0][2], afA[cur].x, bfB[cur].x);
            ffma2(acc[0][3], afA[cur].x, bfB[cur].y);
            ffma2(acc[1][0], afA[cur].y, bfA[cur].x);
            ffma2(acc[1][1], afA[cur].y, bfA[cur].y);
            ffma2(acc[1][2], afA[cur].y, bfB[cur].x);
            ffma2(acc[1][3], afA[cur].y, bfB[cur].y);
            ffma2(acc[2][0], afB[cur].x, bfA[cur].x);
            ffma2(acc[2][1], afB[cur].x, bfA[cur].y);
            ffma2(acc[2][2], afB[cur].x, bfB[cur].x);
            ffma2(acc[2][3], afB[cur].x, bfB[cur].y);
            ffma2(acc[3][0], afB[cur].y, bfA[cur].x);
            ffma2(acc[3][1], afB[cur].y, bfA[cur].y);
            ffma2(acc[3][2], afB[cur].y, bfB[cur].x);
            ffma2(acc[3][3], afB[cur].y, bfB[cur].y);
        }

        if (more) {
            const int nb = buf ^ 1;
            As[nb][(ak + 0) * ASTR + arow] = av.x;
            As[nb][(ak + 1) * ASTR + arow] = av.y;
            As[nb][(ak + 2) * ASTR + arow] = av.z;
            As[nb][(ak + 3) * ASTR + arow] = av.w;
            *(u64*)&Bs[nb][(bk + 0) * BSTR + 2 * bcol] = pack2(b0v.x, b0v.x);
            *(u64*)&Bs[nb][(bk + 1) * BSTR + 2 * bcol] = pack2(b0v.y, b0v.y);
            *(u64*)&Bs[nb][(bk + 2) * BSTR + 2 * bcol] = pack2(b0v.z, b0v.z);
            *(u64*)&Bs[nb][(bk + 3) * BSTR + 2 * bcol] = pack2(b0v.w, b0v.w);
            *(u64*)&Bs[nb][(bk + 4) * BSTR + 2 * bcol] = pack2(b1v.x, b1v.x);
            *(u64*)&Bs[nb][(bk + 5) * BSTR + 2 * bcol] = pack2(b1v.y, b1v.y);
            *(u64*)&Bs[nb][(bk + 6) * BSTR + 2 * bcol] = pack2(b1v.z, b1v.z);
            *(u64*)&Bs[nb][(bk + 7) * BSTR + 2 * bcol] = pack2(b1v.w, b1v.w);
        }
        __syncthreads();
        buf ^= 1;
    }

    // write partials: rows r0+2p (lo) and r0+2p+1 (hi), cols c0..c0+3
    float* zbase = g_zp + (size_t)blockIdx.y * B_ROWS * CHUNK;
#pragma unroll
    for (int p = 0; p < 4; p++) {
        float2 x0 = unpack2(acc[p][0]);
        float2 x1 = unpack2(acc[p][1]);
        float2 x2 = unpack2(acc[p][2]);
        float2 x3 = unpack2(acc[p][3]);
        float4 lo = make_float4(x0.x, x1.x, x2.x, x3.x);
        float4 hi = make_float4(x0.y, x1.y, x2.y, x3.y);
        float* zp = zbase + (size_t)(brow + r0 + 2 * p) * CHUNK + c0;
        *(float4*)zp = lo;
        *(float4*)(zp + CHUNK) = hi;
    }
}

// ---------------------------------------------------------------------------
// Triangular epilogue (rank-1 update form).
// Block: 256 threads = 8 warps; each warp handles 2 batch rows -> 16 rows/block,
// grid = 256 blocks. Smem holds the 128x128 triangular W tile as Ws[c][n]
// (stride 129 -> conflict-free column reads). Lane owns nodes 32q+lane.
// Per step c: broadcast acc (2 shuffles), all lanes compute sigmoid redundantly
// (no return broadcast), then rank-1 update of future accs.
// ---------------------------------------------------------------------------
#define WSTR 129
#define EPI_SMEM (CHUNK * WSTR * 4)

__global__ __launch_bounds__(256) void epi_chunk(const float* __restrict__ W,
                                                 const float* __restrict__ bias,
                                                 int i0)
{
    extern __shared__ float Ws[];          // [128][129]
    const int P    = N_IN + i0;
    const int tid  = threadIdx.x;
    const int warp = tid >> 5;
    const int lane = tid & 31;
    const int m0   = blockIdx.x * 16 + warp * 2;
    const int m1   = m0 + 1;

    // stage triangular tile: Ws[c][n] = W[i0+n][P+c]
    // lanes vary n (consecutive) -> conflict-free STS; LDG is 16B gather (L2-resident)
    for (int i = tid; i < CHUNK * 32; i += 256) {
        int n  = i & 127;
        int c4 = i >> 7;
        float4 v = *(const float4*)&W[(size_t)(i0 + n) * N_NODES + P + 4 * c4];
        float* dst = &Ws[(4 * c4) * WSTR + n];
        dst[0 * WSTR] = v.x;
        dst[1 * WSTR] = v.y;
        dst[2 * WSTR] = v.z;
        dst[3 * WSTR] = v.w;
    }
    __syncthreads();

    // init acc from 4 K-split partials + bias
    float acc[4][2], ov[4][2];
#pragma unroll
    for (int q = 0; q < 4; q++) {
        const int idx = 32 * q + lane;
        float bz = bias[i0 + idx];
        float a0 = bz, a1 = bz;
#pragma unroll
        for (int s = 0; s < KSPLIT; s++) {
            const float* zp = g_zp + (size_t)s * B_ROWS * CHUNK;
            a0 += zp[(size_t)m0 * CHUNK + idx];
            a1 += zp[(size_t)m1 * CHUNK + idx];
        }
        acc[q][0] = a0; acc[q][1] = a1;
        ov[q][0] = 0.f; ov[q][1] = 0.f;
    }

#pragma unroll
    for (int q = 0; q < 4; q++) {
#pragma unroll 4
        for (int cc = 0; cc < 32; cc++) {
            float z0 = __shfl_sync(0xffffffffu, acc[q][0], cc);
            float z1 = __shfl_sync(0xffffffffu, acc[q][1], cc);
            float o0 = sig5(z0);
            float o1 = sig5(z1);
            const int c = 32 * q + cc;
            const float* wr = &Ws[c * WSTR + lane];
            // rank-1 update: only node groups q2 >= q can have nonzero weight
            if (q <= 0) { float w0 = wr[0];
                acc[0][0] = fmaf(w0, o0, acc[0][0]);
                acc[0][1] = fmaf(w0, o1, acc[0][1]); }
            if (q <= 1) { float w1 = wr[32];
                acc[1][0] = fmaf(w1, o0, acc[1][0]);
                acc[1][1] = fmaf(w1, o1, acc[1][1]); }
            if (q <= 2) { float w2 = wr[64];
                acc[2][0] = fmaf(w2, o0, acc[2][0]);
                acc[2][1] = fmaf(w2, o1, acc[2][1]); }
            { float w3 = wr[96];
                acc[3][0] = fmaf(w3, o0, acc[3][0]);
                acc[3][1] = fmaf(w3, o1, acc[3][1]); }
            // owner lane keeps the output
            ov[q][0] = (lane == cc) ? o0 : ov[q][0];
            ov[q][1] = (lane == cc) ? o1 : ov[q][1];
        }
    }

    // write outputs
#pragma unroll
    for (int q = 0; q < 4; q++) {
        const int idx = P + 32 * q + lane;
        g_outputs[(size_t)m0 * N_NODES + idx] = ov[q][0];
        g_outputs[(size_t)m1 * N_NODES + idx] = ov[q][1];
    }
}

// ---------------------------------------------------------------------------
__global__ void init_kernel(const float4* __restrict__ x)
{
    int idx = blockIdx.x * blockDim.x + threadIdx.x;   // over 4096*128 float4s
    if (idx < B_ROWS * (N_IN / 4)) {
        int r = idx >> 7;
        int c = idx & 127;
        ((float4*)g_outputs)[(size_t)r * (N_NODES / 4) + c] = x[idx];
    }
}

__global__ void copy_kernel(float4* __restrict__ out)
{
    int idx = blockIdx.x * blockDim.x + threadIdx.x;   // over 4096*64 float4s
    if (idx < B_ROWS * (N_OUT / 4)) {
        int r = idx >> 6;
        int c = idx & 63;
        out[idx] = ((const float4*)g_outputs)[(size_t)r * (N_NODES / 4) +
                                              (N_NODES - N_OUT) / 4 + c];
    }
}

// ---------------------------------------------------------------------------
extern "C" void kernel_launch(void* const* d_in, const int* in_sizes, int n_in,
                              void* d_out, int out_size)
{
    (void)in_sizes; (void)n_in; (void)out_size;
    const float* x  = (const float*)d_in[0];
    const float* W  = (const float*)d_in[1];
    const float* b  = (const float*)d_in[2];
    float* out = (float*)d_out;

    cudaFuncSetAttribute(epi_chunk, cudaFuncAttributeMaxDynamicSharedMemorySize,
                         EPI_SMEM);

    init_kernel<<<(B_ROWS * (N_IN / 4) + 255) / 256, 256>>>((const float4*)x);
    for (int k = 0; k < NCHUNK; k++) {
        dim3 grid(B_ROWS / BM, KSPLIT);
        gemm_chunk<<<grid, 256>>>(W, k * CHUNK);
        epi_chunk<<<B_ROWS / 16, 256, EPI_SMEM>>>(W, b, k * CHUNK);
    }
    copy_kernel<<<(B_ROWS * (N_OUT / 4) + 255) / 256, 256>>>((float4*)out);
}